// round 14
// baseline (speedup 1.0000x reference)
#include <cuda_runtime.h>
#include <math.h>

// Shape (fixed by the dataset)
#define NB 8
#define NT 4096
#define NH 8
#define ND 64
#define DQ 16                 // float4 lanes over D
#define L 8                   // timesteps per thread
#define SUBS 16               // sub-chunks per tile (block = SUBS*DQ = 256 threads)
#define TILE_T (L * SUBS)     // 128 timesteps per tile
#define NTILES (NT / TILE_T)  // 32  (<= 32: lookback fits in one warp)
#define NBH (NB * NH)         // 64
#define F4T (NH * ND / 4)     // float4 stride between consecutive t = 128
#define SMP 17                // padded smem stride (float4 units)
#define FULLM 0xFFFFFFFFu

// Aggregate-only lookback state. Epoch-tagged flags: ready iff == current epoch,
// so stale state from interrupted launches is ignored (no reset pass needed).
__device__ float4       g_S[NTILES * NBH * DQ];     // tile aggregates
__device__ int          g_flag[NTILES * NBH * 8];   // per (tile, bh, dq-pair warp)
__device__ unsigned int g_epoch;                    // bumped once per launch

static __device__ __forceinline__ void st_release(int* p, int v) {
    asm volatile("st.release.gpu.s32 [%0], %1;" :: "l"(p), "r"(v) : "memory");
}
static __device__ __forceinline__ int ld_acquire(const int* p) {
    int v;
    asm volatile("ld.acquire.gpu.s32 %0, [%1];" : "=r"(v) : "l"(p) : "memory");
    return v;
}
static __device__ __forceinline__ float4 fma4(float s, float4 A, float4 B) {
    return make_float4(fmaf(s, A.x, B.x), fmaf(s, A.y, B.y),
                       fmaf(s, A.z, B.z), fmaf(s, A.w, B.w));
}

__global__ void k_epoch() { atomicAdd(&g_epoch, 1u); }

__global__ __launch_bounds__(256, 4) void k_scan(
    const float4* __restrict__ v, const float4* __restrict__ x,
    const float4* __restrict__ v0, const float* __restrict__ sw,
    float4* __restrict__ out)
{
    __shared__ float4 smT[SUBS * SMP];   // exclusive prefixes (padded)
    __shared__ float4 carry_sm[DQ];

    const int tid  = threadIdx.x;
    const int dq   = tid & 15;
    const int sub  = tid >> 4;           // 0..15
    const int w    = tid >> 5;           // warp id 0..7 (owns dq pair 2w, 2w+1)
    const int lane = tid & 31;
    const int bh   = blockIdx.x;         // channel fastest -> tile-major waves
    const int tile = blockIdx.y;
    const int h    = bh & (NH - 1);
    const int b    = bh >> 3;

    const int epoch = (int)g_epoch;      // constant for the whole launch

    const float a  = 1.0f / (1.0f + expf(-sw[h]));
    const float om = 1.0f - a;
    const float cf = a * (om / fmaxf(om, 1e-6f));
    float a8_1 = a;
    #pragma unroll
    for (int i = 0; i < 3; ++i) a8_1 *= a8_1;          // a^8
    const float a8_2 = a8_1 * a8_1;                    // a^16
    const float a8_4 = a8_2 * a8_2;                    // a^32
    const float a8_8 = a8_4 * a8_4;                    // a^64
    const float aT   = a8_8 * a8_8;                    // a^128 = a^TILE_T

    const int base = ((b * NT + tile * TILE_T + sub * L) * NH + h) * (ND / 4) + dq;

    // ---- phase A: local scan of L steps (zero-seeded) in registers ----
    float4 y[L];
    float4 yy = make_float4(0.f, 0.f, 0.f, 0.f);
    #pragma unroll
    for (int i = 0; i < L; ++i) {
        float4 vv = v[base + i * F4T];
        float4 xx = x[base + i * F4T];
        yy.x = fmaf(a, yy.x, fmaf(om, vv.x, cf * xx.x));
        yy.y = fmaf(a, yy.y, fmaf(om, vv.y, cf * xx.y));
        yy.z = fmaf(a, yy.z, fmaf(om, vv.z, cf * xx.z));
        yy.w = fmaf(a, yy.w, fmaf(om, vv.w, cf * xx.w));
        y[i] = yy;
    }
    smT[sub * SMP + dq] = yy;
    __syncthreads();

    // ---- phase B: warp w KS-scans the 16 sub-aggregates of its dq pair ----
    // lanes: s = lane&15 (sub-chunk), half = lane>>4 -> dq = 2w+half
    const int s   = lane & 15;
    const int dqp = w * 2 + (lane >> 4);
    float4 I = smT[s * SMP + dqp];
    {
        float f = a8_1;
        #pragma unroll
        for (int o = 1; o < 16; o <<= 1) {
            float4 t;
            t.x = __shfl_up_sync(FULLM, I.x, o, 16);
            t.y = __shfl_up_sync(FULLM, I.y, o, 16);
            t.z = __shfl_up_sync(FULLM, I.z, o, 16);
            t.w = __shfl_up_sync(FULLM, I.w, o, 16);
            if (s >= o) I = fma4(f, t, I);
            f *= f;
        }
    }
    // tile aggregates for both dq of the pair (inclusive totals at s==15)
    float4 g0, g1;
    g0.x = __shfl_sync(FULLM, I.x, 15); g0.y = __shfl_sync(FULLM, I.y, 15);
    g0.z = __shfl_sync(FULLM, I.z, 15); g0.w = __shfl_sync(FULLM, I.w, 15);
    g1.x = __shfl_sync(FULLM, I.x, 31); g1.y = __shfl_sync(FULLM, I.y, 31);
    g1.z = __shfl_sync(FULLM, I.z, 31); g1.w = __shfl_sync(FULLM, I.w, 31);

    const int sidx = (tile * NBH + bh) * DQ + w * 2;
    const int fidx = (tile * NBH + bh) * 8 + w;
    // publish both aggregates IMMEDIATELY (single thread: stores before release)
    if (lane == 31) {
        __stcg(&g_S[sidx],     g0);
        __stcg(&g_S[sidx + 1], g1);
        st_release(&g_flag[fidx], epoch);
    }
    // exclusive prefix: entry state of sub-chunk s (zero tile seed) = I_{s-1}
    float4 E;
    E.x = __shfl_up_sync(FULLM, I.x, 1, 16);
    E.y = __shfl_up_sync(FULLM, I.y, 1, 16);
    E.z = __shfl_up_sync(FULLM, I.z, 1, 16);
    E.w = __shfl_up_sync(FULLM, I.w, 1, 16);
    if (s == 0) E = make_float4(0.f, 0.f, 0.f, 0.f);
    smT[s * SMP + dqp] = E;

    // ---- phase C: aggregate-only parallel lookback (no P-chain) ----
    // carry_t = sum_{k<t} aT^k S[t-1-k]  +  aT^t v0     (lane k handles hop k)
    float4 s0 = make_float4(0.f, 0.f, 0.f, 0.f);
    float4 s1 = make_float4(0.f, 0.f, 0.f, 0.f);
    {
        const float aT2 = aT * aT, aT4 = aT2 * aT2, aT8 = aT4 * aT4, aT16 = aT8 * aT8;
        float dj = 1.0f;                 // aT^lane from bits (exact products)
        if (lane & 1)  dj *= aT;
        if (lane & 2)  dj *= aT2;
        if (lane & 4)  dj *= aT4;
        if (lane & 8)  dj *= aT8;
        if (lane & 16) dj *= aT16;
        if (lane < tile) {
            const int pf = ((tile - 1 - lane) * NBH + bh) * 8 + w;
            const int ps = ((tile - 1 - lane) * NBH + bh) * DQ + w * 2;
            while (ld_acquire(&g_flag[pf]) != epoch) __nanosleep(40);
            s0 = fma4(dj, __ldcg(&g_S[ps]),     s0);
            s1 = fma4(dj, __ldcg(&g_S[ps + 1]), s1);
        } else if (lane == tile) {
            s0 = fma4(dj, __ldg(&v0[h * DQ + w * 2]),     s0);
            s1 = fma4(dj, __ldg(&v0[h * DQ + w * 2 + 1]), s1);
        }
        __syncwarp(FULLM);
        #pragma unroll
        for (int o = 16; o >= 1; o >>= 1) {
            s0.x += __shfl_xor_sync(FULLM, s0.x, o);
            s0.y += __shfl_xor_sync(FULLM, s0.y, o);
            s0.z += __shfl_xor_sync(FULLM, s0.z, o);
            s0.w += __shfl_xor_sync(FULLM, s0.w, o);
            s1.x += __shfl_xor_sync(FULLM, s1.x, o);
            s1.y += __shfl_xor_sync(FULLM, s1.y, o);
            s1.z += __shfl_xor_sync(FULLM, s1.z, o);
            s1.w += __shfl_xor_sync(FULLM, s1.w, o);
        }
    }
    if (lane == 0) {
        carry_sm[w * 2]     = s0;
        carry_sm[w * 2 + 1] = s1;
    }
    __syncthreads();

    // ---- phase D: apply carry in registers, single store pass ----
    const float4 carry = carry_sm[dq];
    const float4 E2 = smT[sub * SMP + dq];
    float p = 1.0f;                      // a8^sub from bits (exact products)
    if (sub & 1) p *= a8_1;
    if (sub & 2) p *= a8_2;
    if (sub & 4) p *= a8_4;
    if (sub & 8) p *= a8_8;
    const float4 c = fma4(p, carry, E2);

    float pa = a;
    #pragma unroll
    for (int i = 0; i < L; ++i) {
        out[base + i * F4T] = fma4(pa, c, y[i]);
        pa *= a;
    }
}

extern "C" void kernel_launch(void* const* d_in, const int* in_sizes, int n_in,
                              void* d_out, int out_size)
{
    const float4* v  = (const float4*)d_in[0];   // values   [B,T,H,D] f32
    const float4* x  = (const float4*)d_in[1];   // aux      [B,T,H,D] f32
    const float4* v0 = (const float4*)d_in[2];   // v0       [1,1,H,D] f32
    const float*  sw = (const float*)d_in[3];    // weight   [H,1]     f32

    k_epoch<<<1, 1>>>();
    k_scan<<<dim3(NBH, NTILES), SUBS * DQ>>>(v, x, (const float4*)v0, sw, (float4*)d_out);
}